// round 5
// baseline (speedup 1.0000x reference)
#include <cuda_runtime.h>
#include <math.h>

// Problem constants (fixed shapes for RNN_55405078119028)
#define T_DIM 256
#define B_DIM 256
#define I_DIM 9
#define H_DIM 1024
#define A_DIM 4
#define R_DIM 38

// Tile config for the recurrent step GEMM: 32x64 output tiles, K-tile 16.
#define TM 32
#define TN 64
#define TK 16

// Scratch: rbias[B,H] = reward @ r2h + bh  (constant across timesteps)
__device__ float g_rbias[B_DIM * H_DIM];

// ---------------------------------------------------------------------------
// P1: rbias = reward @ r2h + bh      (B*H threads, 38 MACs each — trivial)
// ---------------------------------------------------------------------------
__global__ void rbias_kernel(const float* __restrict__ reward,
                             const float* __restrict__ r2h,
                             const float* __restrict__ bh) {
    int idx = blockIdx.x * blockDim.x + threadIdx.x;   // = b*H + h
    int h = idx & (H_DIM - 1);
    int b = idx >> 10;
    float s = bh[h];
    const float* rw = reward + b * R_DIM;
#pragma unroll
    for (int j = 0; j < R_DIM; ++j)
        s = fmaf(rw[j], r2h[j * H_DIM + h], s);
    g_rbias[idx] = s;
}

// Decode k_action robustly whether it landed as int32 or float32.
__device__ __forceinline__ float decode_k(const void* p) {
    int   iv = *(const int*)p;
    float fv = __int_as_float(iv);
    float af = fabsf(fv);
    // A genuine float scalar will be a "normal" magnitude; an int reinterpreted
    // as float is denormal/huge. k==0 falls through to (float)iv == 0 correctly.
    if (af >= 1e-30f && af <= 1e30f) return fv;
    return (float)iv;
}

// ---------------------------------------------------------------------------
// P2: pre[t,b,h] = inputs[t,b]@i2h + k*actions[t,b]@a2h + rbias[b,h]
//     written directly into d_out (overwritten in-place by the recurrence).
//     HBM-bound on the 268MB write (~35us).
// ---------------------------------------------------------------------------
__global__ void pre_kernel(const float* __restrict__ inputs,
                           const float* __restrict__ actions,
                           const float* __restrict__ i2h,
                           const float* __restrict__ a2h,
                           const void*  __restrict__ kact_ptr,
                           float* __restrict__ out) {
    unsigned idx = blockIdx.x * blockDim.x + threadIdx.x;  // t*B*H + b*H + h
    int h  = idx & (H_DIM - 1);
    unsigned tb = idx >> 10;                               // t*B + b
    float k = decode_k(kact_ptr);

    float s = g_rbias[idx & (B_DIM * H_DIM - 1)];
    const float* inp = inputs + (size_t)tb * I_DIM;
    const float* act = actions + (size_t)tb * A_DIM;
#pragma unroll
    for (int i = 0; i < I_DIM; ++i)
        s = fmaf(inp[i], i2h[i * H_DIM + h], s);
#pragma unroll
    for (int a = 0; a < A_DIM; ++a)
        s = fmaf(k * act[a], a2h[a * H_DIM + h], s);
    out[idx] = s;
}

// NaN-safe fast tanh: 1 - 2/(e^{2x}+1).
//   x -> +inf : e = inf -> 1.  x -> -inf : e = 0 -> -1.  No clamp needed.
__device__ __forceinline__ float tanh_fast(float x) {
    float e = __expf(2.0f * x);
    return 1.0f - __fdividef(2.0f, e + 1.0f);
}

// ---------------------------------------------------------------------------
// Step kernel: cur (holds pre[t]) <- blend(tanh(pre[t] + prev @ W), prev, r)
//   Grid: 128 blocks = 8 row-tiles (B/32) x 16 col-tiles (H/64)
//   Block: 256 threads, thread tile 2x4, smem-tiled K loop (TK=16).
// ---------------------------------------------------------------------------
__global__ void __launch_bounds__(256)
step_kernel(const float* __restrict__ prev,   // [B,H]  hidden[t-1]
            const float* __restrict__ W,      // [H,H]  h2h
            const float* __restrict__ rr,     // [H]    inertia r
            float* __restrict__ cur)          // [B,H]  pre in, hidden out
{
    __shared__ __align__(8)  float As[TK][34];   // A^T tile, padded (even stride)
    __shared__ __align__(16) float Bs[TK][TN];

    const int bm   = blockIdx.x & 7;         // row tile
    const int bn   = blockIdx.x >> 3;        // col tile
    const int row0 = bm * TM;
    const int col0 = bn * TN;

    const int tid = threadIdx.x;
    const int tx  = tid & 15;                // 16 col groups (4 cols each)
    const int ty  = tid >> 4;                // 16 row groups (2 rows each)

    // smem load indexing
    const int kq = tid & 15;                 // k within tile
    const int rq = tid >> 4;                 // row within tile (0..15; +16 second)
    const int kB = tid >> 4;                 // k row for B loads
    const int nB = (tid & 15) * 4;           // 4-col group for B loads

    float acc00 = 0.f, acc01 = 0.f, acc02 = 0.f, acc03 = 0.f;
    float acc10 = 0.f, acc11 = 0.f, acc12 = 0.f, acc13 = 0.f;

    const float* Aballoc = prev + (size_t)row0 * H_DIM;
    const float* Wb      = W + col0;

    for (int k0 = 0; k0 < H_DIM; k0 += TK) {
        // A tile (transposed into smem): 32 rows x 16 k
        As[kq][rq]      = Aballoc[(size_t)rq        * H_DIM + k0 + kq];
        As[kq][rq + 16] = Aballoc[(size_t)(rq + 16) * H_DIM + k0 + kq];
        // B tile: 16 k x 64 n, vectorized
        float4 w4 = *(const float4*)&Wb[(size_t)(k0 + kB) * H_DIM + nB];
        *(float4*)&Bs[kB][nB] = w4;
        __syncthreads();

#pragma unroll
        for (int kk = 0; kk < TK; ++kk) {
            float2 a = *(const float2*)&As[kk][2 * ty];
            float4 b = *(const float4*)&Bs[kk][4 * tx];
            acc00 = fmaf(a.x, b.x, acc00);
            acc01 = fmaf(a.x, b.y, acc01);
            acc02 = fmaf(a.x, b.z, acc02);
            acc03 = fmaf(a.x, b.w, acc03);
            acc10 = fmaf(a.y, b.x, acc10);
            acc11 = fmaf(a.y, b.y, acc11);
            acc12 = fmaf(a.y, b.z, acc12);
            acc13 = fmaf(a.y, b.w, acc13);
        }
        __syncthreads();
    }

    // Epilogue: out = (1-r)*tanh(pre + acc) + r*prev  (in-place over pre tile)
    const int r0 = row0 + 2 * ty;
    const int c0 = col0 + 4 * tx;
    float4 rv = *(const float4*)&rr[c0];

    {
        float4 pre4 = *(const float4*)&cur[(size_t)r0 * H_DIM + c0];
        float4 pv   = *(const float4*)&prev[(size_t)r0 * H_DIM + c0];
        float4 o;
        float c;
        c = tanh_fast(pre4.x + acc00); o.x = c + rv.x * (pv.x - c);
        c = tanh_fast(pre4.y + acc01); o.y = c + rv.y * (pv.y - c);
        c = tanh_fast(pre4.z + acc02); o.z = c + rv.z * (pv.z - c);
        c = tanh_fast(pre4.w + acc03); o.w = c + rv.w * (pv.w - c);
        *(float4*)&cur[(size_t)r0 * H_DIM + c0] = o;
    }
    {
        int row = r0 + 1;
        float4 pre4 = *(const float4*)&cur[(size_t)row * H_DIM + c0];
        float4 pv   = *(const float4*)&prev[(size_t)row * H_DIM + c0];
        float4 o;
        float c;
        c = tanh_fast(pre4.x + acc10); o.x = c + rv.x * (pv.x - c);
        c = tanh_fast(pre4.y + acc11); o.y = c + rv.y * (pv.y - c);
        c = tanh_fast(pre4.z + acc12); o.z = c + rv.z * (pv.z - c);
        c = tanh_fast(pre4.w + acc13); o.w = c + rv.w * (pv.w - c);
        *(float4*)&cur[(size_t)row * H_DIM + c0] = o;
    }
}

// ---------------------------------------------------------------------------
// Launch: rbias -> pre (into d_out) -> 256 sequential step kernels.
// All plain stream launches: graph-capturable, allocation-free, deterministic.
// ---------------------------------------------------------------------------
extern "C" void kernel_launch(void* const* d_in, const int* in_sizes, int n_in,
                              void* d_out, int out_size) {
    const float* inputs  = (const float*)d_in[0];
    const float* hidden0 = (const float*)d_in[1];
    const float* actions = (const float*)d_in[2];
    const float* reward  = (const float*)d_in[3];
    const float* i2h     = (const float*)d_in[4];
    const float* h2h     = (const float*)d_in[5];
    const float* a2h     = (const float*)d_in[6];
    const float* r2h     = (const float*)d_in[7];
    const float* bh      = (const float*)d_in[8];
    const float* r       = (const float*)d_in[9];
    const void*  kact    = d_in[10];
    float* out = (float*)d_out;

    // P1: rbias
    rbias_kernel<<<(B_DIM * H_DIM) / 256, 256>>>(reward, r2h, bh);

    // P2: pre for all timesteps, straight into d_out
    unsigned total = (unsigned)T_DIM * B_DIM * H_DIM;   // 67,108,864
    pre_kernel<<<total / 256, 256>>>(inputs, actions, i2h, a2h, kact, out);

    // Recurrence: d_out[t] = blend(tanh(d_out[t] + d_out[t-1] @ h2h))
    const float* prev = hidden0;
    for (int t = 0; t < T_DIM; ++t) {
        float* cur = out + (size_t)t * B_DIM * H_DIM;
        step_kernel<<<128, 256>>>(prev, h2h, r, cur);
        prev = cur;
    }
}

// round 7
// speedup vs baseline: 1.4554x; 1.4554x over previous
#include <cuda_runtime.h>
#include <cuda_bf16.h>
#include <cstdint>
#include <math.h>

// Problem constants
#define T_DIM 256
#define B_DIM 256
#define I_DIM 9
#define H_DIM 1024
#define A_DIM 4
#define R_DIM 38

// ---------------------------------------------------------------------------
// Device scratch (no allocation allowed anywhere)
// ---------------------------------------------------------------------------
__device__ float          g_rbias[B_DIM * H_DIM];        // 1 MB
__device__ __nv_bfloat16  g_Whi[H_DIM * H_DIM];          // [N][K] transposed, 2 MB
__device__ __nv_bfloat16  g_Wlo[H_DIM * H_DIM];          // [N][K] transposed, 2 MB
__device__ __nv_bfloat16  g_A[2][B_DIM * 2 * H_DIM];     // [b][hi(1024)|lo(1024)] ping-pong

// ---------------------------------------------------------------------------
// Small prep kernels
// ---------------------------------------------------------------------------
__global__ void rbias_kernel(const float* __restrict__ reward,
                             const float* __restrict__ r2h,
                             const float* __restrict__ bh) {
    int idx = blockIdx.x * blockDim.x + threadIdx.x;   // b*H + h
    int h = idx & (H_DIM - 1);
    int b = idx >> 10;
    float s = bh[h];
    const float* rw = reward + b * R_DIM;
#pragma unroll
    for (int j = 0; j < R_DIM; ++j)
        s = fmaf(rw[j], r2h[j * H_DIM + h], s);
    g_rbias[idx] = s;
}

// W transpose + bf16 hi/lo split: g_W*[n][k] = split(h2h[k][n])
__global__ void wprep_kernel(const float* __restrict__ h2h) {
    int idx = blockIdx.x * blockDim.x + threadIdx.x;   // k*H + n (coalesced read)
    int n = idx & (H_DIM - 1);
    int k = idx >> 10;
    float w = h2h[(size_t)k * H_DIM + n];
    __nv_bfloat16 hi = __float2bfloat16(w);
    __nv_bfloat16 lo = __float2bfloat16(w - __bfloat162float(hi));
    g_Whi[(size_t)n * H_DIM + k] = hi;
    g_Wlo[(size_t)n * H_DIM + k] = lo;
}

__global__ void conv_h0_kernel(const float* __restrict__ hidden0) {
    int idx = blockIdx.x * blockDim.x + threadIdx.x;   // b*H + h
    int h = idx & (H_DIM - 1);
    int b = idx >> 10;
    float v = hidden0[idx];
    __nv_bfloat16 hi = __float2bfloat16(v);
    __nv_bfloat16 lo = __float2bfloat16(v - __bfloat162float(hi));
    g_A[0][(size_t)b * 2048 + h]        = hi;
    g_A[0][(size_t)b * 2048 + 1024 + h] = lo;
}

__device__ __forceinline__ float decode_k(const void* p) {
    int iv = *(const int*)p;
    float fv = __int_as_float(iv);
    float af = fabsf(fv);
    if (af >= 1e-30f && af <= 1e30f) return fv;
    return (float)iv;
}

// pre[t,b,h] -> d_out (overwritten in place by the recurrence)
__global__ void pre_kernel(const float* __restrict__ inputs,
                           const float* __restrict__ actions,
                           const float* __restrict__ i2h,
                           const float* __restrict__ a2h,
                           const void*  __restrict__ kact_ptr,
                           float* __restrict__ out) {
    unsigned idx = blockIdx.x * blockDim.x + threadIdx.x;
    int h = idx & (H_DIM - 1);
    unsigned tb = idx >> 10;
    float k = decode_k(kact_ptr);
    float s = g_rbias[idx & (B_DIM * H_DIM - 1)];
    const float* inp = inputs + (size_t)tb * I_DIM;
    const float* act = actions + (size_t)tb * A_DIM;
#pragma unroll
    for (int i = 0; i < I_DIM; ++i) s = fmaf(inp[i], i2h[i * H_DIM + h], s);
#pragma unroll
    for (int a = 0; a < A_DIM; ++a) s = fmaf(k * act[a], a2h[a * H_DIM + h], s);
    out[idx] = s;
}

__device__ __forceinline__ float tanh_fast(float x) {
    float e = __expf(2.0f * x);
    return 1.0f - __fdividef(2.0f, e + 1.0f);
}

__device__ __forceinline__ uint32_t smem_u32(const void* p) {
    uint32_t a;
    asm("{ .reg .u64 t; cvta.to.shared.u64 t, %1; cvt.u32.u64 %0, t; }" : "=r"(a) : "l"(p));
    return a;
}

#define CP_ASYNC16(dst, src) \
    asm volatile("cp.async.cg.shared.global [%0], [%1], 16;" :: "r"(dst), "l"(src))
#define CP_COMMIT() asm volatile("cp.async.commit_group;" ::: "memory")
#define CP_WAIT(n)  asm volatile("cp.async.wait_group %0;" :: "n"(n) : "memory")

__device__ __forceinline__ void mma16816(float* c, const uint32_t* a, const uint32_t* b) {
    asm volatile(
        "mma.sync.aligned.m16n8k16.row.col.f32.bf16.bf16.f32 "
        "{%0,%1,%2,%3}, {%4,%5,%6,%7}, {%8,%9}, {%0,%1,%2,%3};"
        : "+f"(c[0]), "+f"(c[1]), "+f"(c[2]), "+f"(c[3])
        : "r"(a[0]), "r"(a[1]), "r"(a[2]), "r"(a[3]), "r"(b[0]), "r"(b[1]));
}

// ---------------------------------------------------------------------------
// Step kernel: cur <- blend(tanh(pre + prev@W), prev, r), HMMA bf16 split-GEMM.
//   Logical K = 3072: pass0 hi*Whi, pass1 lo*Whi, pass2 hi*Wlo.
//   CTA: 64x64 tile, 128 threads (2x2 warps of 32x32). Grid 64 = 4 x 16.
//   K-chunks of 64, cp.async double-buffered. 48 chunks total.
//   smem padded stride 36 words -> conflict-free fragment LDS.
// ---------------------------------------------------------------------------
#define NCHUNK 48
#define SSTRIDE 36

__global__ void __launch_bounds__(128, 1)
step_gemm(int par,
          const float* __restrict__ prev,
          const float* __restrict__ rr,
          float* __restrict__ cur) {
    __shared__ uint32_t sA[2][64 * SSTRIDE];
    __shared__ uint32_t sB[2][64 * SSTRIDE];

    const int tid  = threadIdx.x;
    const int wid  = tid >> 5;
    const int lane = tid & 31;
    const int gid  = lane >> 2;      // 0..7
    const int tig  = lane & 3;       // 0..3
    const int wr   = wid >> 1;       // warp row 0..1 (32 rows each)
    const int wc   = wid & 1;        // warp col 0..1 (32 cols each)
    const int m0   = (blockIdx.x & 3) * 64;
    const int n0   = (blockIdx.x >> 2) * 64;

    const __nv_bfloat16* __restrict__ A     = g_A[par];
    __nv_bfloat16* __restrict__       Anext = g_A[par ^ 1];

    float acc[2][4][4];
#pragma unroll
    for (int mt = 0; mt < 2; ++mt)
#pragma unroll
        for (int nt = 0; nt < 4; ++nt)
#pragma unroll
            for (int q = 0; q < 4; ++q) acc[mt][nt][q] = 0.f;

    // cp.async a full K-chunk (A: 64x64 bf16, B: 64x64 bf16) into buffer `buf`
    auto issue = [&](int i, int buf) {
        const int p  = i >> 4;         // pass
        const int ko = (i & 15) << 6;  // k offset within 1024
        const __nv_bfloat16* Ab = A + (size_t)m0 * 2048 + ((p == 1) ? 1024 : 0) + ko;
        const __nv_bfloat16* Wb = ((p == 2) ? g_Wlo : g_Whi) + (size_t)n0 * H_DIM + ko;
#pragma unroll
        for (int j = 0; j < 4; ++j) {
            int idx = tid + (j << 7);
            int row = idx >> 3, seg = idx & 7;
            CP_ASYNC16(smem_u32(&sA[buf][row * SSTRIDE + seg * 4]),
                       (const void*)(Ab + (size_t)row * 2048 + seg * 8));
            CP_ASYNC16(smem_u32(&sB[buf][row * SSTRIDE + seg * 4]),
                       (const void*)(Wb + (size_t)row * H_DIM + seg * 8));
        }
        CP_COMMIT();
    };

    issue(0, 0);
    issue(1, 1);

    for (int i = 0; i < NCHUNK; ++i) {
        if (i < NCHUNK - 2) { CP_WAIT(1); } else { CP_WAIT(0); }
        __syncthreads();

        const uint32_t* __restrict__ wA = sA[i & 1];
        const uint32_t* __restrict__ wB = sB[i & 1];
#pragma unroll
        for (int k16 = 0; k16 < 4; ++k16) {
            const int kb2 = k16 * 8;
            uint32_t af[2][4];
#pragma unroll
            for (int mt = 0; mt < 2; ++mt) {
                int r0 = wr * 32 + mt * 16 + gid;
                af[mt][0] = wA[r0 * SSTRIDE + kb2 + tig];
                af[mt][1] = wA[(r0 + 8) * SSTRIDE + kb2 + tig];
                af[mt][2] = wA[r0 * SSTRIDE + kb2 + 4 + tig];
                af[mt][3] = wA[(r0 + 8) * SSTRIDE + kb2 + 4 + tig];
            }
            uint32_t bf_[4][2];
#pragma unroll
            for (int nt = 0; nt < 4; ++nt) {
                int n = wc * 32 + nt * 8 + gid;
                bf_[nt][0] = wB[n * SSTRIDE + kb2 + tig];
                bf_[nt][1] = wB[n * SSTRIDE + kb2 + 4 + tig];
            }
#pragma unroll
            for (int mt = 0; mt < 2; ++mt)
#pragma unroll
                for (int nt = 0; nt < 4; ++nt)
                    mma16816(acc[mt][nt], af[mt], bf_[nt]);
        }
        __syncthreads();
        if (i + 2 < NCHUNK) issue(i + 2, i & 1);
    }

    // Epilogue: tanh + leaky blend, in-place over pre; emit bf16 hi/lo for next A
#pragma unroll
    for (int mt = 0; mt < 2; ++mt) {
#pragma unroll
        for (int nt = 0; nt < 4; ++nt) {
            const int col = n0 + wc * 32 + nt * 8 + 2 * tig;
            const float2 rv = *(const float2*)&rr[col];
#pragma unroll
            for (int half = 0; half < 2; ++half) {
                const int row = m0 + wr * 32 + mt * 16 + gid + half * 8;
                const float cx = acc[mt][nt][half * 2 + 0];
                const float cy = acc[mt][nt][half * 2 + 1];
                float* cp = cur + (size_t)row * H_DIM + col;
                const float* pp = prev + (size_t)row * H_DIM + col;
                float2 pre2 = *(const float2*)cp;
                float2 pv   = *(const float2*)pp;
                float t, h0, h1;
                t = tanh_fast(pre2.x + cx); h0 = t + rv.x * (pv.x - t);
                t = tanh_fast(pre2.y + cy); h1 = t + rv.y * (pv.y - t);
                *(float2*)cp = make_float2(h0, h1);

                __nv_bfloat16 a0 = __float2bfloat16(h0);
                __nv_bfloat16 a1 = __float2bfloat16(h1);
                __nv_bfloat16* hip = Anext + (size_t)row * 2048 + col;
                *(__nv_bfloat162*)hip = __nv_bfloat162(a0, a1);
                __nv_bfloat16 l0 = __float2bfloat16(h0 - __bfloat162float(a0));
                __nv_bfloat16 l1 = __float2bfloat16(h1 - __bfloat162float(a1));
                *(__nv_bfloat162*)(hip + 1024) = __nv_bfloat162(l0, l1);
            }
        }
    }
}

// ---------------------------------------------------------------------------
// Launch: prep -> pre -> 256 sequential step kernels (graph-capturable).
// ---------------------------------------------------------------------------
extern "C" void kernel_launch(void* const* d_in, const int* in_sizes, int n_in,
                              void* d_out, int out_size) {
    const float* inputs  = (const float*)d_in[0];
    const float* hidden0 = (const float*)d_in[1];
    const float* actions = (const float*)d_in[2];
    const float* reward  = (const float*)d_in[3];
    const float* i2h     = (const float*)d_in[4];
    const float* h2h     = (const float*)d_in[5];
    const float* a2h     = (const float*)d_in[6];
    const float* r2h     = (const float*)d_in[7];
    const float* bh      = (const float*)d_in[8];
    const float* r       = (const float*)d_in[9];
    const void*  kact    = d_in[10];
    float* out = (float*)d_out;

    rbias_kernel<<<(B_DIM * H_DIM) / 256, 256>>>(reward, r2h, bh);
    wprep_kernel<<<(H_DIM * H_DIM) / 256, 256>>>(h2h);
    conv_h0_kernel<<<(B_DIM * H_DIM) / 256, 256>>>(hidden0);

    unsigned total = (unsigned)T_DIM * B_DIM * H_DIM;
    pre_kernel<<<total / 256, 256>>>(inputs, actions, i2h, a2h, kact, out);

    const float* prev = hidden0;
    for (int t = 0; t < T_DIM; ++t) {
        float* cur = out + (size_t)t * B_DIM * H_DIM;
        step_gemm<<<64, 128>>>(t & 1, prev, r, cur);
        prev = cur;
    }
}

// round 8
// speedup vs baseline: 1.9696x; 1.3533x over previous
#include <cuda_runtime.h>
#include <cuda_bf16.h>
#include <cstdint>
#include <math.h>

// Problem constants
#define T_DIM 256
#define B_DIM 256
#define I_DIM 9
#define H_DIM 1024
#define A_DIM 4
#define R_DIM 38

#define GRID_P 128          // persistent grid: 4 M-tiles x 32 N-tiles

// ---------------------------------------------------------------------------
// Device scratch (no allocation allowed anywhere)
// ---------------------------------------------------------------------------
__device__ float          g_rbias[B_DIM * H_DIM];        // 1 MB
__device__ __nv_bfloat16  g_Whi[H_DIM * H_DIM];          // [N][K] transposed hi
__device__ __nv_bfloat16  g_Wlo[H_DIM * H_DIM];          // [N][K] transposed lo
__device__ __nv_bfloat16  g_A[2][B_DIM * 2 * H_DIM];     // hidden hi|lo, ping-pong
__device__ unsigned       g_bar[T_DIM];                  // per-step barrier counters

// ---------------------------------------------------------------------------
// Prep kernels
// ---------------------------------------------------------------------------
__global__ void rbias_kernel(const float* __restrict__ reward,
                             const float* __restrict__ r2h,
                             const float* __restrict__ bh) {
    int idx = blockIdx.x * blockDim.x + threadIdx.x;   // b*H + h
    int h = idx & (H_DIM - 1);
    int b = idx >> 10;
    float s = bh[h];
    const float* rw = reward + b * R_DIM;
#pragma unroll
    for (int j = 0; j < R_DIM; ++j)
        s = fmaf(rw[j], r2h[j * H_DIM + h], s);
    g_rbias[idx] = s;
}

// Tiled transpose + hi/lo split: g_W*[n][k] = split(h2h[k][n]). Coalesced both sides.
__global__ void wprep_kernel(const float* __restrict__ h2h) {
    __shared__ float tile[32][33];
    const int k0 = blockIdx.x * 32;
    const int n0 = blockIdx.y * 32;
    const int tid = threadIdx.x;
#pragma unroll
    for (int it = 0; it < 4; ++it) {
        int e = it * 256 + tid;
        int kk = e >> 5, nn = e & 31;
        tile[kk][nn] = h2h[(size_t)(k0 + kk) * H_DIM + n0 + nn];
    }
    __syncthreads();
#pragma unroll
    for (int it = 0; it < 2; ++it) {
        int e = it * 256 + tid;       // 512 bf16x2 stores
        int nn = e >> 4, pp = e & 15;
        float w0 = tile[2 * pp][nn];
        float w1 = tile[2 * pp + 1][nn];
        __nv_bfloat16 h0 = __float2bfloat16(w0);
        __nv_bfloat16 h1 = __float2bfloat16(w1);
        __nv_bfloat16 l0 = __float2bfloat16(w0 - __bfloat162float(h0));
        __nv_bfloat16 l1 = __float2bfloat16(w1 - __bfloat162float(h1));
        size_t o = (size_t)(n0 + nn) * H_DIM + k0 + 2 * pp;
        *(__nv_bfloat162*)&g_Whi[o] = __nv_bfloat162(h0, h1);
        *(__nv_bfloat162*)&g_Wlo[o] = __nv_bfloat162(l0, l1);
    }
}

__global__ void conv_h0_kernel(const float* __restrict__ hidden0) {
    int idx = blockIdx.x * blockDim.x + threadIdx.x;   // b*H + h
    int h = idx & (H_DIM - 1);
    int b = idx >> 10;
    float v = hidden0[idx];
    __nv_bfloat16 hi = __float2bfloat16(v);
    __nv_bfloat16 lo = __float2bfloat16(v - __bfloat162float(hi));
    g_A[0][(size_t)b * 2048 + h]        = hi;
    g_A[0][(size_t)b * 2048 + 1024 + h] = lo;
}

__global__ void zero_bar_kernel() { g_bar[threadIdx.x] = 0u; }

__device__ __forceinline__ float decode_k(const void* p) {
    int iv = *(const int*)p;
    float fv = __int_as_float(iv);
    float af = fabsf(fv);
    if (af >= 1e-30f && af <= 1e30f) return fv;
    return (float)iv;
}

// pre[t,b,:] per block; float4 math, smem-staged per-row scalars.
__global__ void pre_kernel(const float* __restrict__ inputs,
                           const float* __restrict__ actions,
                           const float* __restrict__ i2h,
                           const float* __restrict__ a2h,
                           const void*  __restrict__ kact_ptr,
                           float* __restrict__ out) {
    __shared__ float sin[I_DIM], sact[A_DIM], sk;
    const int tb = blockIdx.x;           // t*B + b
    const int tid = threadIdx.x;
    if (tid < I_DIM) sin[tid] = inputs[(size_t)tb * I_DIM + tid];
    else if (tid < I_DIM + A_DIM) sact[tid - I_DIM] = actions[(size_t)tb * A_DIM + (tid - I_DIM)];
    else if (tid == I_DIM + A_DIM) sk = decode_k(kact_ptr);
    __syncthreads();
    const int h = tid * 4;
    const int b = tb & (B_DIM - 1);
    float4 s = *(const float4*)&g_rbias[b * H_DIM + h];
#pragma unroll
    for (int i = 0; i < I_DIM; ++i) {
        float4 w = *(const float4*)&i2h[i * H_DIM + h];
        float x = sin[i];
        s.x = fmaf(x, w.x, s.x); s.y = fmaf(x, w.y, s.y);
        s.z = fmaf(x, w.z, s.z); s.w = fmaf(x, w.w, s.w);
    }
    const float k = sk;
#pragma unroll
    for (int a = 0; a < A_DIM; ++a) {
        float4 w = *(const float4*)&a2h[a * H_DIM + h];
        float x = k * sact[a];
        s.x = fmaf(x, w.x, s.x); s.y = fmaf(x, w.y, s.y);
        s.z = fmaf(x, w.z, s.z); s.w = fmaf(x, w.w, s.w);
    }
    *(float4*)&out[(size_t)tb * H_DIM + h] = s;
}

// ---------------------------------------------------------------------------
// Persistent recurrence kernel
// ---------------------------------------------------------------------------
__device__ __forceinline__ float tanh_fast(float x) {
    float e = __expf(2.0f * x);
    return 1.0f - __fdividef(2.0f, e + 1.0f);
}
__device__ __forceinline__ uint32_t smem_u32(const void* p) {
    uint32_t a;
    asm("{ .reg .u64 t; cvta.to.shared.u64 t, %1; cvt.u32.u64 %0, t; }" : "=r"(a) : "l"(p));
    return a;
}
#define CP_ASYNC16(dst, src) \
    asm volatile("cp.async.cg.shared.global [%0], [%1], 16;" :: "r"(dst), "l"(src))
#define CP_COMMIT() asm volatile("cp.async.commit_group;" ::: "memory")
#define CP_WAIT(n)  asm volatile("cp.async.wait_group %0;" :: "n"(n) : "memory")

__device__ __forceinline__ void mma16816(float* c, const uint32_t* a, const uint32_t* b) {
    asm volatile(
        "mma.sync.aligned.m16n8k16.row.col.f32.bf16.bf16.f32 "
        "{%0,%1,%2,%3}, {%4,%5,%6,%7}, {%8,%9}, {%0,%1,%2,%3};"
        : "+f"(c[0]), "+f"(c[1]), "+f"(c[2]), "+f"(c[3])
        : "r"(a[0]), "r"(a[1]), "r"(a[2]), "r"(a[3]), "r"(b[0]), "r"(b[1]));
}

// smem word layout: Whi[32][516] @0, Wlo @16512, A buf0 @33024 (64x36), buf1 @35328
#define WS_STRIDE 516
#define WLO_OFF   16512
#define A0_OFF    33024
#define A1_OFF    35328
#define A_STRIDE  36
#define SMEM_P_WORDS 37632
#define SMEM_P_BYTES (SMEM_P_WORDS * 4)
#define NCHUNK 48

__global__ void __launch_bounds__(256, 1)
rnn_persistent(const float* __restrict__ hidden0,
               const float* __restrict__ rr,
               float* __restrict__ out) {
    extern __shared__ uint32_t smw[];
    const int tid  = threadIdx.x;
    const int wid  = tid >> 5;
    const int lane = tid & 31;
    const int gid  = lane >> 2;          // 0..7
    const int tig  = lane & 3;           // 0..3
    const int wm   = wid >> 1;           // 0..3  (16-row slabs)
    const int wn   = wid & 1;            // 0..1  (16-col slabs)
    const int n_grp = blockIdx.x & 31;
    const int m_grp = blockIdx.x >> 5;
    const int m0 = m_grp * 64;
    const int n0 = n_grp * 32;

    // ---- W slice (hi+lo) into smem, once ----
    for (int e = tid; e < 32 * 128; e += 256) {
        int n = e >> 7, c = e & 127;                 // c: uint4 (8 bf16) within K row
        uint4 vh = *(const uint4*)&g_Whi[(size_t)(n0 + n) * H_DIM + c * 8];
        uint4 vl = *(const uint4*)&g_Wlo[(size_t)(n0 + n) * H_DIM + c * 8];
        *(uint4*)&smw[n * WS_STRIDE + c * 4]           = vh;
        *(uint4*)&smw[WLO_OFF + n * WS_STRIDE + c * 4] = vl;
    }

    // ---- prev hidden tile + inertia in registers ----
    float hprev[2][4];
    float2 rv[2];
#pragma unroll
    for (int nt = 0; nt < 2; ++nt) {
        int c = n0 + wn * 16 + nt * 8 + tig * 2;
        rv[nt] = *(const float2*)&rr[c];
#pragma unroll
        for (int half = 0; half < 2; ++half) {
            int row = m0 + wm * 16 + gid + half * 8;
            float2 hp = *(const float2*)&hidden0[(size_t)row * H_DIM + c];
            hprev[nt][half * 2]     = hp.x;
            hprev[nt][half * 2 + 1] = hp.y;
        }
    }
    __syncthreads();

    for (int t = 0; t < T_DIM; ++t) {
        const __nv_bfloat16* __restrict__ A     = g_A[t & 1];
        __nv_bfloat16* __restrict__       Anext = g_A[(t + 1) & 1];
        float* __restrict__ outt = out + (size_t)t * (B_DIM * H_DIM);

        float acc[2][4];
#pragma unroll
        for (int nt = 0; nt < 2; ++nt)
#pragma unroll
            for (int q = 0; q < 4; ++q) acc[nt][q] = 0.f;

        auto issue = [&](int i, int buf) {
            const int p  = i >> 4;                 // pass: hi*Whi, lo*Whi, hi*Wlo
            const int ko = (i & 15) << 6;          // k offset (bf16) within 1024
            const __nv_bfloat16* Ab = A + (size_t)m0 * 2048 + ((p == 1) ? 1024 : 0) + ko;
            const uint32_t base = smem_u32(&smw[buf ? A1_OFF : A0_OFF]);
#pragma unroll
            for (int j = 0; j < 2; ++j) {
                int idx = tid + (j << 8);
                int row = idx >> 3, seg = idx & 7;
                CP_ASYNC16(base + (uint32_t)(row * A_STRIDE + seg * 4) * 4,
                           (const void*)(Ab + (size_t)row * 2048 + seg * 8));
            }
            CP_COMMIT();
        };

        issue(0, 0);
        issue(1, 1);

        for (int i = 0; i < NCHUNK; ++i) {
            if (i < NCHUNK - 2) { CP_WAIT(1); } else { CP_WAIT(0); }
            __syncthreads();

            const int p = i >> 4;
            const uint32_t* __restrict__ wA = &smw[(i & 1) ? A1_OFF : A0_OFF];
            const uint32_t* __restrict__ wB = &smw[(p == 2) ? WLO_OFF : 0];
            const int kwbase = (i & 15) << 5;      // word offset of chunk in W rows

#pragma unroll
            for (int k16 = 0; k16 < 4; ++k16) {
                const int ka = k16 * 8;            // A smem word offset (within chunk)
                const int kb = kwbase + k16 * 8;   // W smem word offset (full K row)
                uint32_t af[4];
                const int r0 = wm * 16 + gid;
                af[0] = wA[r0 * A_STRIDE + ka + tig];
                af[1] = wA[(r0 + 8) * A_STRIDE + ka + tig];
                af[2] = wA[r0 * A_STRIDE + ka + 4 + tig];
                af[3] = wA[(r0 + 8) * A_STRIDE + ka + 4 + tig];
                uint32_t bf_[2][2];
#pragma unroll
                for (int nt = 0; nt < 2; ++nt) {
                    int n = wn * 16 + nt * 8 + gid;
                    bf_[nt][0] = wB[n * WS_STRIDE + kb + tig];
                    bf_[nt][1] = wB[n * WS_STRIDE + kb + 4 + tig];
                }
#pragma unroll
                for (int nt = 0; nt < 2; ++nt)
                    mma16816(acc[nt], af, bf_[nt]);
            }
            __syncthreads();
            if (i + 2 < NCHUNK) issue(i + 2, i & 1);
        }

        // ---- epilogue: tanh + leaky blend (prev in regs), emit next A hi/lo ----
#pragma unroll
        for (int nt = 0; nt < 2; ++nt) {
            const int c = n0 + wn * 16 + nt * 8 + tig * 2;
#pragma unroll
            for (int half = 0; half < 2; ++half) {
                const int row = m0 + wm * 16 + gid + half * 8;
                float* cp = outt + (size_t)row * H_DIM + c;
                float2 pre2 = *(const float2*)cp;
                float tt, h0, h1;
                tt = tanh_fast(pre2.x + acc[nt][half * 2]);
                h0 = tt + rv[nt].x * (hprev[nt][half * 2] - tt);
                tt = tanh_fast(pre2.y + acc[nt][half * 2 + 1]);
                h1 = tt + rv[nt].y * (hprev[nt][half * 2 + 1] - tt);
                *(float2*)cp = make_float2(h0, h1);
                hprev[nt][half * 2]     = h0;
                hprev[nt][half * 2 + 1] = h1;

                __nv_bfloat16 a0 = __float2bfloat16(h0);
                __nv_bfloat16 a1 = __float2bfloat16(h1);
                __nv_bfloat16* hip = Anext + (size_t)row * 2048 + c;
                *(__nv_bfloat162*)hip = __nv_bfloat162(a0, a1);
                __nv_bfloat16 l0 = __float2bfloat16(h0 - __bfloat162float(a0));
                __nv_bfloat16 l1 = __float2bfloat16(h1 - __bfloat162float(a1));
                *(__nv_bfloat162*)(hip + 1024) = __nv_bfloat162(l0, l1);
            }
        }

        // ---- grid barrier (publish g_A[t+1] before anyone reads it) ----
        if (t < T_DIM - 1) {
            __threadfence();
            __syncthreads();
            if (tid == 0) {
                atomicAdd(&g_bar[t], 1u);
                volatile unsigned* bp = &g_bar[t];
                while (*bp < (unsigned)GRID_P) { }
            }
            __syncthreads();
        }
    }
}

// ---------------------------------------------------------------------------
// Launch: prep -> pre -> ONE persistent kernel (graph-capturable, alloc-free)
// ---------------------------------------------------------------------------
extern "C" void kernel_launch(void* const* d_in, const int* in_sizes, int n_in,
                              void* d_out, int out_size) {
    const float* inputs  = (const float*)d_in[0];
    const float* hidden0 = (const float*)d_in[1];
    const float* actions = (const float*)d_in[2];
    const float* reward  = (const float*)d_in[3];
    const float* i2h     = (const float*)d_in[4];
    const float* h2h     = (const float*)d_in[5];
    const float* a2h     = (const float*)d_in[6];
    const float* r2h     = (const float*)d_in[7];
    const float* bh      = (const float*)d_in[8];
    const float* r       = (const float*)d_in[9];
    const void*  kact    = d_in[10];
    float* out = (float*)d_out;

    static int attr_done = 0;
    if (!attr_done) {
        cudaFuncSetAttribute(rnn_persistent,
                             cudaFuncAttributeMaxDynamicSharedMemorySize, SMEM_P_BYTES);
        attr_done = 1;
    }

    rbias_kernel<<<(B_DIM * H_DIM) / 256, 256>>>(reward, r2h, bh);
    wprep_kernel<<<dim3(32, 32), 256>>>(h2h);
    conv_h0_kernel<<<(B_DIM * H_DIM) / 256, 256>>>(hidden0);
    zero_bar_kernel<<<1, T_DIM>>>();

    pre_kernel<<<T_DIM * B_DIM, 256>>>(inputs, actions, i2h, a2h, kact, out);

    rnn_persistent<<<GRID_P, 256, SMEM_P_BYTES>>>(hidden0, r, out);
}

// round 9
// speedup vs baseline: 2.9931x; 1.5196x over previous
#include <cuda_runtime.h>
#include <cuda_bf16.h>
#include <cstdint>
#include <math.h>

// Problem constants
#define T_DIM 256
#define B_DIM 256
#define I_DIM 9
#define H_DIM 1024
#define A_DIM 4
#define R_DIM 38

#define GRID_P 128          // persistent grid: 4 M-tiles x 32 N-tiles

// ---------------------------------------------------------------------------
// Device scratch
// ---------------------------------------------------------------------------
__device__ float          g_rbias[B_DIM * H_DIM];
__device__ __nv_bfloat16  g_Whi[H_DIM * H_DIM];          // [N][K] hi
__device__ __nv_bfloat16  g_Wlo[H_DIM * H_DIM];          // [N][K] lo
__device__ __nv_bfloat16  g_A[2][B_DIM * 2 * H_DIM];     // hidden hi|lo ping-pong
__device__ unsigned       g_bar[T_DIM * 4];              // per-step, per-Mgroup

// ---------------------------------------------------------------------------
// Prep kernels
// ---------------------------------------------------------------------------
__global__ void rbias_kernel(const float* __restrict__ reward,
                             const float* __restrict__ r2h,
                             const float* __restrict__ bh) {
    int idx = blockIdx.x * blockDim.x + threadIdx.x;
    int h = idx & (H_DIM - 1);
    int b = idx >> 10;
    float s = bh[h];
    const float* rw = reward + b * R_DIM;
#pragma unroll
    for (int j = 0; j < R_DIM; ++j)
        s = fmaf(rw[j], r2h[j * H_DIM + h], s);
    g_rbias[idx] = s;
}

__global__ void wprep_kernel(const float* __restrict__ h2h) {
    __shared__ float tile[32][33];
    const int k0 = blockIdx.x * 32;
    const int n0 = blockIdx.y * 32;
    const int tid = threadIdx.x;
#pragma unroll
    for (int it = 0; it < 4; ++it) {
        int e = it * 256 + tid;
        int kk = e >> 5, nn = e & 31;
        tile[kk][nn] = h2h[(size_t)(k0 + kk) * H_DIM + n0 + nn];
    }
    __syncthreads();
#pragma unroll
    for (int it = 0; it < 2; ++it) {
        int e = it * 256 + tid;
        int nn = e >> 4, pp = e & 15;
        float w0 = tile[2 * pp][nn];
        float w1 = tile[2 * pp + 1][nn];
        __nv_bfloat16 h0 = __float2bfloat16(w0);
        __nv_bfloat16 h1 = __float2bfloat16(w1);
        __nv_bfloat16 l0 = __float2bfloat16(w0 - __bfloat162float(h0));
        __nv_bfloat16 l1 = __float2bfloat16(w1 - __bfloat162float(h1));
        size_t o = (size_t)(n0 + nn) * H_DIM + k0 + 2 * pp;
        *(__nv_bfloat162*)&g_Whi[o] = __nv_bfloat162(h0, h1);
        *(__nv_bfloat162*)&g_Wlo[o] = __nv_bfloat162(l0, l1);
    }
}

__global__ void conv_h0_kernel(const float* __restrict__ hidden0) {
    int idx = blockIdx.x * blockDim.x + threadIdx.x;
    int h = idx & (H_DIM - 1);
    int b = idx >> 10;
    float v = hidden0[idx];
    __nv_bfloat16 hi = __float2bfloat16(v);
    __nv_bfloat16 lo = __float2bfloat16(v - __bfloat162float(hi));
    g_A[0][(size_t)b * 2048 + h]        = hi;
    g_A[0][(size_t)b * 2048 + 1024 + h] = lo;
}

__global__ void zero_bar_kernel() { g_bar[threadIdx.x] = 0u; }

__device__ __forceinline__ float decode_k(const void* p) {
    int iv = *(const int*)p;
    float fv = __int_as_float(iv);
    float af = fabsf(fv);
    if (af >= 1e-30f && af <= 1e30f) return fv;
    return (float)iv;
}

__global__ void pre_kernel(const float* __restrict__ inputs,
                           const float* __restrict__ actions,
                           const float* __restrict__ i2h,
                           const float* __restrict__ a2h,
                           const void*  __restrict__ kact_ptr,
                           float* __restrict__ out) {
    __shared__ float sin[I_DIM], sact[A_DIM], sk;
    const int tb = blockIdx.x;
    const int tid = threadIdx.x;
    if (tid < I_DIM) sin[tid] = inputs[(size_t)tb * I_DIM + tid];
    else if (tid < I_DIM + A_DIM) sact[tid - I_DIM] = actions[(size_t)tb * A_DIM + (tid - I_DIM)];
    else if (tid == I_DIM + A_DIM) sk = decode_k(kact_ptr);
    __syncthreads();
    const int h = tid * 4;
    const int b = tb & (B_DIM - 1);
    float4 s = *(const float4*)&g_rbias[b * H_DIM + h];
#pragma unroll
    for (int i = 0; i < I_DIM; ++i) {
        float4 w = *(const float4*)&i2h[i * H_DIM + h];
        float x = sin[i];
        s.x = fmaf(x, w.x, s.x); s.y = fmaf(x, w.y, s.y);
        s.z = fmaf(x, w.z, s.z); s.w = fmaf(x, w.w, s.w);
    }
    const float k = sk;
#pragma unroll
    for (int a = 0; a < A_DIM; ++a) {
        float4 w = *(const float4*)&a2h[a * H_DIM + h];
        float x = k * sact[a];
        s.x = fmaf(x, w.x, s.x); s.y = fmaf(x, w.y, s.y);
        s.z = fmaf(x, w.z, s.z); s.w = fmaf(x, w.w, s.w);
    }
    *(float4*)&out[(size_t)tb * H_DIM + h] = s;
}

// ---------------------------------------------------------------------------
// Persistent recurrence kernel
// ---------------------------------------------------------------------------
__device__ __forceinline__ float tanh_fast(float x) {
    float e = __expf(2.0f * x);
    return 1.0f - __fdividef(2.0f, e + 1.0f);
}
__device__ __forceinline__ uint32_t smem_u32(const void* p) {
    uint32_t a;
    asm("{ .reg .u64 t; cvta.to.shared.u64 t, %1; cvt.u32.u64 %0, t; }" : "=r"(a) : "l"(p));
    return a;
}
#define CP_ASYNC16(dst, src) \
    asm volatile("cp.async.cg.shared.global [%0], [%1], 16;" :: "r"(dst), "l"(src))
#define CP_COMMIT() asm volatile("cp.async.commit_group;" ::: "memory")
#define CP_WAIT(n)  asm volatile("cp.async.wait_group %0;" :: "n"(n) : "memory")

__device__ __forceinline__ void mma16816(float* c, const uint32_t* a, const uint32_t* b) {
    asm volatile(
        "mma.sync.aligned.m16n8k16.row.col.f32.bf16.bf16.f32 "
        "{%0,%1,%2,%3}, {%4,%5,%6,%7}, {%8,%9}, {%0,%1,%2,%3};"
        : "+f"(c[0]), "+f"(c[1]), "+f"(c[2]), "+f"(c[3])
        : "r"(a[0]), "r"(a[1]), "r"(a[2]), "r"(a[3]), "r"(b[0]), "r"(b[1]));
}
__device__ __forceinline__ void ldsm4(uint32_t* r, uint32_t addr) {
    asm volatile("ldmatrix.sync.aligned.m8n8.x4.shared.b16 {%0,%1,%2,%3}, [%4];"
        : "=r"(r[0]), "=r"(r[1]), "=r"(r[2]), "=r"(r[3]) : "r"(addr));
}

// smem words: Whi[32][516] @0, Wlo @16512, A ring: 4 bufs of 64x36 @33024
#define WS_STRIDE 516
#define WLO_OFF   16512
#define ABUF_OFF  33024
#define ABUF_SZ   2304
#define A_STRIDE  36
#define SMEM_P_WORDS (ABUF_OFF + 4 * ABUF_SZ)        // 42240
#define SMEM_P_BYTES (SMEM_P_WORDS * 4)              // 168960
#define NCHUNK 32

__global__ void __launch_bounds__(256, 1)
rnn_persistent(const float* __restrict__ hidden0,
               const float* __restrict__ rr,
               float* __restrict__ out) {
    extern __shared__ uint32_t smw[];
    const int tid  = threadIdx.x;
    const int wid  = tid >> 5;
    const int lane = tid & 31;
    const int gid  = lane >> 2;
    const int tig  = lane & 3;
    const int wm   = wid >> 1;           // 0..3 (16-row slabs)
    const int wn   = wid & 1;            // 0..1 (16-col slabs)
    const int n_grp = blockIdx.x & 31;
    const int m_grp = blockIdx.x >> 5;
    const int m0 = m_grp * 64;
    const int n0 = n_grp * 32;

    // ---- W slice (hi+lo) into smem once ----
    for (int e = tid; e < 32 * 128; e += 256) {
        int n = e >> 7, c = e & 127;
        uint4 vh = *(const uint4*)&g_Whi[(size_t)(n0 + n) * H_DIM + c * 8];
        uint4 vl = *(const uint4*)&g_Wlo[(size_t)(n0 + n) * H_DIM + c * 8];
        *(uint4*)&smw[n * WS_STRIDE + c * 4]           = vh;
        *(uint4*)&smw[WLO_OFF + n * WS_STRIDE + c * 4] = vl;
    }

    // ---- prev hidden tile + inertia in registers ----
    float hprev[2][4];
    float2 rv[2];
#pragma unroll
    for (int nt = 0; nt < 2; ++nt) {
        int c = n0 + wn * 16 + nt * 8 + tig * 2;
        rv[nt] = *(const float2*)&rr[c];
#pragma unroll
        for (int half = 0; half < 2; ++half) {
            int row = m0 + wm * 16 + gid + half * 8;
            float2 hp = *(const float2*)&hidden0[(size_t)row * H_DIM + c];
            hprev[nt][half * 2]     = hp.x;
            hprev[nt][half * 2 + 1] = hp.y;
        }
    }

    // ldmatrix lane addresses (word offsets), computed once
    const uint32_t sbase = smem_u32(smw);
    // A: row = wm*16 + (lane&15), col word = ka + (lane>>4)*4
    const int a_lane_off = (wm * 16 + (lane & 15)) * A_STRIDE + ((lane >> 4) << 2);
    // B: row = wn*16 + (lane&7) + ((lane>>4)<<3), col word = kb + ((lane>>3)&1)*4
    const int b_lane_row = wn * 16 + (lane & 7) + ((lane >> 4) << 3);
    const int b_lane_off = b_lane_row * WS_STRIDE + (((lane >> 3) & 1) << 2);

    __syncthreads();

    for (int t = 0; t < T_DIM; ++t) {
        const __nv_bfloat16* __restrict__ A     = g_A[t & 1];
        __nv_bfloat16* __restrict__       Anext = g_A[(t + 1) & 1];
        float* __restrict__ outt = out + (size_t)t * (B_DIM * H_DIM);

        float acc[2][4];
#pragma unroll
        for (int nt = 0; nt < 2; ++nt)
#pragma unroll
            for (int q = 0; q < 4; ++q) acc[nt][q] = 0.f;

        // chunk i: i<16 -> A-hi chunk i (vs Whi AND Wlo); i>=16 -> A-lo (vs Whi)
        auto issue = [&](int i) {
            const int buf = i & 3;
            const __nv_bfloat16* Ab = A + (size_t)m0 * 2048
                                        + ((i >= 16) ? 1024 : 0) + ((i & 15) << 6);
            const uint32_t base = sbase + (uint32_t)(ABUF_OFF + buf * ABUF_SZ) * 4;
#pragma unroll
            for (int j = 0; j < 2; ++j) {
                int idx = tid + (j << 8);
                int row = idx >> 3, seg = idx & 7;
                CP_ASYNC16(base + (uint32_t)(row * A_STRIDE + seg * 4) * 4,
                           (const void*)(Ab + (size_t)row * 2048 + seg * 8));
            }
            CP_COMMIT();
        };

        issue(0); issue(1); issue(2);

        for (int i = 0; i < NCHUNK; ++i) {
            if (i < NCHUNK - 2)      { CP_WAIT(2); }
            else if (i == NCHUNK - 2){ CP_WAIT(1); }
            else                     { CP_WAIT(0); }
            __syncthreads();

            const int abuf_w = ABUF_OFF + (i & 3) * ABUF_SZ;
            const int kw = (i & 15) << 5;          // chunk word offset in W rows
            const bool hi = (i < 16);

#pragma unroll
            for (int k16 = 0; k16 < 4; ++k16) {
                uint32_t af[4];
                ldsm4(af, sbase + (uint32_t)(abuf_w + a_lane_off + k16 * 8) * 4);
                const int kb = kw + k16 * 8;
                uint32_t bh_[4];
                ldsm4(bh_, sbase + (uint32_t)(b_lane_off + kb) * 4);
                mma16816(acc[0], af, bh_);
                mma16816(acc[1], af, bh_ + 2);
                if (hi) {
                    uint32_t bl_[4];
                    ldsm4(bl_, sbase + (uint32_t)(WLO_OFF + b_lane_off + kb) * 4);
                    mma16816(acc[0], af, bl_);
                    mma16816(acc[1], af, bl_ + 2);
                }
            }
            if (i + 3 < NCHUNK) issue(i + 3);
        }

        // ---- epilogue: tanh + leaky blend (prev in regs), emit next A hi/lo ----
#pragma unroll
        for (int nt = 0; nt < 2; ++nt) {
            const int c = n0 + wn * 16 + nt * 8 + tig * 2;
#pragma unroll
            for (int half = 0; half < 2; ++half) {
                const int row = m0 + wm * 16 + gid + half * 8;
                float* cp = outt + (size_t)row * H_DIM + c;
                float2 pre2 = *(const float2*)cp;
                float tt, h0, h1;
                tt = tanh_fast(pre2.x + acc[nt][half * 2]);
                h0 = tt + rv[nt].x * (hprev[nt][half * 2] - tt);
                tt = tanh_fast(pre2.y + acc[nt][half * 2 + 1]);
                h1 = tt + rv[nt].y * (hprev[nt][half * 2 + 1] - tt);
                *(float2*)cp = make_float2(h0, h1);
                hprev[nt][half * 2]     = h0;
                hprev[nt][half * 2 + 1] = h1;

                __nv_bfloat16 a0 = __float2bfloat16(h0);
                __nv_bfloat16 a1 = __float2bfloat16(h1);
                __nv_bfloat16* hip = Anext + (size_t)row * 2048 + c;
                *(__nv_bfloat162*)hip = __nv_bfloat162(a0, a1);
                __nv_bfloat16 l0 = __float2bfloat16(h0 - __bfloat162float(a0));
                __nv_bfloat16 l1 = __float2bfloat16(h1 - __bfloat162float(a1));
                *(__nv_bfloat162*)(hip + 1024) = __nv_bfloat162(l0, l1);
            }
        }

        // ---- per-Mgroup barrier: only the 32 CTAs sharing this Mtile ----
        if (t < T_DIM - 1) {
            __threadfence();
            __syncthreads();
            if (tid == 0) {
                unsigned* bp = &g_bar[t * 4 + m_grp];
                atomicAdd(bp, 1u);
                while (*(volatile unsigned*)bp < 32u) { __nanosleep(50); }
            }
            __syncthreads();
            __threadfence();
        }
    }
}

// ---------------------------------------------------------------------------
// Launch
// ---------------------------------------------------------------------------
extern "C" void kernel_launch(void* const* d_in, const int* in_sizes, int n_in,
                              void* d_out, int out_size) {
    const float* inputs  = (const float*)d_in[0];
    const float* hidden0 = (const float*)d_in[1];
    const float* actions = (const float*)d_in[2];
    const float* reward  = (const float*)d_in[3];
    const float* i2h     = (const float*)d_in[4];
    const float* h2h     = (const float*)d_in[5];
    const float* a2h     = (const float*)d_in[6];
    const float* r2h     = (const float*)d_in[7];
    const float* bh      = (const float*)d_in[8];
    const float* r       = (const float*)d_in[9];
    const void*  kact    = d_in[10];
    float* out = (float*)d_out;

    static int attr_done = 0;
    if (!attr_done) {
        cudaFuncSetAttribute(rnn_persistent,
                             cudaFuncAttributeMaxDynamicSharedMemorySize, SMEM_P_BYTES);
        attr_done = 1;
    }

    rbias_kernel<<<(B_DIM * H_DIM) / 256, 256>>>(reward, r2h, bh);
    wprep_kernel<<<dim3(32, 32), 256>>>(h2h);
    conv_h0_kernel<<<(B_DIM * H_DIM) / 256, 256>>>(hidden0);
    zero_bar_kernel<<<1, T_DIM * 4>>>();

    pre_kernel<<<T_DIM * B_DIM, 256>>>(inputs, actions, i2h, a2h, kact, out);

    rnn_persistent<<<GRID_P, 256, SMEM_P_BYTES>>>(hidden0, r, out);
}

// round 10
// speedup vs baseline: 3.1163x; 1.0412x over previous
#include <cuda_runtime.h>
#include <cuda_bf16.h>
#include <cstdint>
#include <math.h>

// Problem constants
#define T_DIM 256
#define B_DIM 256
#define I_DIM 9
#define H_DIM 1024
#define A_DIM 4
#define R_DIM 38

#define GRID_P 128          // persistent grid: 4 M-tiles x 32 N-tiles

// ---------------------------------------------------------------------------
// Device scratch
// ---------------------------------------------------------------------------
__device__ float          g_rbias[B_DIM * H_DIM];
__device__ __nv_bfloat16  g_Whi[H_DIM * H_DIM];          // [N][K] hi
__device__ __nv_bfloat16  g_Wlo[H_DIM * H_DIM];          // [N][K] lo
__device__ __nv_bfloat16  g_A[2][B_DIM * 2 * H_DIM];     // hidden hi|lo ping-pong
__device__ unsigned       g_rdy[T_DIM * 4 * 8];          // dataflow counters

// ---------------------------------------------------------------------------
// Prep kernels
// ---------------------------------------------------------------------------
__global__ void rbias_kernel(const float* __restrict__ reward,
                             const float* __restrict__ r2h,
                             const float* __restrict__ bh) {
    int idx = blockIdx.x * blockDim.x + threadIdx.x;
    int h = idx & (H_DIM - 1);
    int b = idx >> 10;
    float s = bh[h];
    const float* rw = reward + b * R_DIM;
#pragma unroll
    for (int j = 0; j < R_DIM; ++j)
        s = fmaf(rw[j], r2h[j * H_DIM + h], s);
    g_rbias[idx] = s;
}

__global__ void wprep_kernel(const float* __restrict__ h2h) {
    __shared__ float tile[32][33];
    const int k0 = blockIdx.x * 32;
    const int n0 = blockIdx.y * 32;
    const int tid = threadIdx.x;
#pragma unroll
    for (int it = 0; it < 4; ++it) {
        int e = it * 256 + tid;
        int kk = e >> 5, nn = e & 31;
        tile[kk][nn] = h2h[(size_t)(k0 + kk) * H_DIM + n0 + nn];
    }
    __syncthreads();
#pragma unroll
    for (int it = 0; it < 2; ++it) {
        int e = it * 256 + tid;
        int nn = e >> 4, pp = e & 15;
        float w0 = tile[2 * pp][nn];
        float w1 = tile[2 * pp + 1][nn];
        __nv_bfloat16 h0 = __float2bfloat16(w0);
        __nv_bfloat16 h1 = __float2bfloat16(w1);
        __nv_bfloat16 l0 = __float2bfloat16(w0 - __bfloat162float(h0));
        __nv_bfloat16 l1 = __float2bfloat16(w1 - __bfloat162float(h1));
        size_t o = (size_t)(n0 + nn) * H_DIM + k0 + 2 * pp;
        *(__nv_bfloat162*)&g_Whi[o] = __nv_bfloat162(h0, h1);
        *(__nv_bfloat162*)&g_Wlo[o] = __nv_bfloat162(l0, l1);
    }
}

__global__ void conv_h0_kernel(const float* __restrict__ hidden0) {
    int idx = blockIdx.x * blockDim.x + threadIdx.x;
    int h = idx & (H_DIM - 1);
    int b = idx >> 10;
    float v = hidden0[idx];
    __nv_bfloat16 hi = __float2bfloat16(v);
    __nv_bfloat16 lo = __float2bfloat16(v - __bfloat162float(hi));
    g_A[0][(size_t)b * 2048 + h]        = hi;
    g_A[0][(size_t)b * 2048 + 1024 + h] = lo;
}

__global__ void zero_rdy_kernel() {
    g_rdy[blockIdx.x * 1024 + threadIdx.x] = 0u;
}

__device__ __forceinline__ float decode_k(const void* p) {
    int iv = *(const int*)p;
    float fv = __int_as_float(iv);
    float af = fabsf(fv);
    if (af >= 1e-30f && af <= 1e30f) return fv;
    return (float)iv;
}

__global__ void pre_kernel(const float* __restrict__ inputs,
                           const float* __restrict__ actions,
                           const float* __restrict__ i2h,
                           const float* __restrict__ a2h,
                           const void*  __restrict__ kact_ptr,
                           float* __restrict__ out) {
    __shared__ float sin[I_DIM], sact[A_DIM], sk;
    const int tb = blockIdx.x;
    const int tid = threadIdx.x;
    if (tid < I_DIM) sin[tid] = inputs[(size_t)tb * I_DIM + tid];
    else if (tid < I_DIM + A_DIM) sact[tid - I_DIM] = actions[(size_t)tb * A_DIM + (tid - I_DIM)];
    else if (tid == I_DIM + A_DIM) sk = decode_k(kact_ptr);
    __syncthreads();
    const int h = tid * 4;
    const int b = tb & (B_DIM - 1);
    float4 s = *(const float4*)&g_rbias[b * H_DIM + h];
#pragma unroll
    for (int i = 0; i < I_DIM; ++i) {
        float4 w = *(const float4*)&i2h[i * H_DIM + h];
        float x = sin[i];
        s.x = fmaf(x, w.x, s.x); s.y = fmaf(x, w.y, s.y);
        s.z = fmaf(x, w.z, s.z); s.w = fmaf(x, w.w, s.w);
    }
    const float k = sk;
#pragma unroll
    for (int a = 0; a < A_DIM; ++a) {
        float4 w = *(const float4*)&a2h[a * H_DIM + h];
        float x = k * sact[a];
        s.x = fmaf(x, w.x, s.x); s.y = fmaf(x, w.y, s.y);
        s.z = fmaf(x, w.z, s.z); s.w = fmaf(x, w.w, s.w);
    }
    *(float4*)&out[(size_t)tb * H_DIM + h] = s;
}

// ---------------------------------------------------------------------------
// Persistent recurrence kernel
// ---------------------------------------------------------------------------
__device__ __forceinline__ float tanh_fast(float x) {
    float e = __expf(2.0f * x);
    return 1.0f - __fdividef(2.0f, e + 1.0f);
}
__device__ __forceinline__ uint32_t smem_u32(const void* p) {
    uint32_t a;
    asm("{ .reg .u64 t; cvta.to.shared.u64 t, %1; cvt.u32.u64 %0, t; }" : "=r"(a) : "l"(p));
    return a;
}
__device__ __forceinline__ unsigned ld_acq(const unsigned* p) {
    unsigned v;
    asm volatile("ld.acquire.gpu.global.u32 %0, [%1];" : "=r"(v) : "l"(p) : "memory");
    return v;
}
#define CP_ASYNC16(dst, src) \
    asm volatile("cp.async.cg.shared.global [%0], [%1], 16;" :: "r"(dst), "l"(src))
#define CP_COMMIT() asm volatile("cp.async.commit_group;" ::: "memory")
#define CP_WAIT(n)  asm volatile("cp.async.wait_group %0;" :: "n"(n) : "memory")

__device__ __forceinline__ void mma16816(float* c, const uint32_t* a, const uint32_t* b) {
    asm volatile(
        "mma.sync.aligned.m16n8k16.row.col.f32.bf16.bf16.f32 "
        "{%0,%1,%2,%3}, {%4,%5,%6,%7}, {%8,%9}, {%0,%1,%2,%3};"
        : "+f"(c[0]), "+f"(c[1]), "+f"(c[2]), "+f"(c[3])
        : "r"(a[0]), "r"(a[1]), "r"(a[2]), "r"(a[3]), "r"(b[0]), "r"(b[1]));
}
__device__ __forceinline__ void ldsm4(uint32_t* r, uint32_t addr) {
    asm volatile("ldmatrix.sync.aligned.m8n8.x4.shared.b16 {%0,%1,%2,%3}, [%4];"
        : "=r"(r[0]), "=r"(r[1]), "=r"(r[2]), "=r"(r[3]) : "r"(addr));
}

// smem words: Whi[32][516] @0, Wlo @16512, A ring: 4 bufs of 64x68 @33024
#define WS_STRIDE 516
#define WLO_OFF   16512
#define ABUF_OFF  33024
#define ABUF_SZ   4352
#define A_STRIDE  68
#define SMEM_P_WORDS (ABUF_OFF + 4 * ABUF_SZ)        // 50432
#define SMEM_P_BYTES (SMEM_P_WORDS * 4)              // 201728
#define NCHUNK 16

__global__ void __launch_bounds__(256, 1)
rnn_persistent(const float* __restrict__ hidden0,
               const float* __restrict__ rr,
               float* __restrict__ out) {
    extern __shared__ uint32_t smw[];
    const int tid  = threadIdx.x;
    const int wid  = tid >> 5;
    const int lane = tid & 31;
    const int gid  = lane >> 2;
    const int tig  = lane & 3;
    const int wm   = wid >> 1;           // 0..3 (16-row slabs)
    const int wn   = wid & 1;            // 0..1 (16-col slabs)
    const int n_grp = blockIdx.x & 31;
    const int m_grp = blockIdx.x >> 5;
    const int m0 = m_grp * 64;
    const int n0 = n_grp * 32;

    // ---- W slice (hi+lo) into smem once ----
    for (int e = tid; e < 32 * 128; e += 256) {
        int n = e >> 7, c = e & 127;
        uint4 vh = *(const uint4*)&g_Whi[(size_t)(n0 + n) * H_DIM + c * 8];
        uint4 vl = *(const uint4*)&g_Wlo[(size_t)(n0 + n) * H_DIM + c * 8];
        *(uint4*)&smw[n * WS_STRIDE + c * 4]           = vh;
        *(uint4*)&smw[WLO_OFF + n * WS_STRIDE + c * 4] = vl;
    }

    // ---- prev hidden tile + inertia in registers ----
    float hprev[2][4];
    float2 rv[2];
#pragma unroll
    for (int nt = 0; nt < 2; ++nt) {
        int c = n0 + wn * 16 + nt * 8 + tig * 2;
        rv[nt] = *(const float2*)&rr[c];
#pragma unroll
        for (int half = 0; half < 2; ++half) {
            int row = m0 + wm * 16 + gid + half * 8;
            float2 hp = *(const float2*)&hidden0[(size_t)row * H_DIM + c];
            hprev[nt][half * 2]     = hp.x;
            hprev[nt][half * 2 + 1] = hp.y;
        }
    }

    // ldmatrix lane word-offsets (fixed)
    const uint32_t sbase = smem_u32(smw);
    const int a_lane_off = (wm * 16 + (lane & 15)) * A_STRIDE + ((lane >> 4) << 2);
    const int b_lane_row = wn * 16 + (lane & 7) + ((lane >> 4) << 3);
    const int b_lane_off = b_lane_row * WS_STRIDE + (((lane >> 3) & 1) << 2);

    __syncthreads();

    for (int t = 0; t < T_DIM; ++t) {
        const __nv_bfloat16* __restrict__ A     = g_A[t & 1];
        __nv_bfloat16* __restrict__       Anext = g_A[(t + 1) & 1];
        float* __restrict__ outt = out + (size_t)t * (B_DIM * H_DIM);

        float acc[2][4];
#pragma unroll
        for (int nt = 0; nt < 2; ++nt)
#pragma unroll
            for (int q = 0; q < 4; ++q) acc[nt][q] = 0.f;

        // Prefetch pre tile into registers (hidden under the GEMM)
        float2 pre_r[2][2];
#pragma unroll
        for (int nt = 0; nt < 2; ++nt) {
            const int c = n0 + wn * 16 + nt * 8 + tig * 2;
#pragma unroll
            for (int half = 0; half < 2; ++half) {
                const int row = m0 + wm * 16 + gid + half * 8;
                pre_r[nt][half] = *(const float2*)(outt + (size_t)row * H_DIM + c);
            }
        }

        // dataflow wait: chunk c (c<8) gated by 4 producers of its 128-col group
        auto wait_c = [&](int c) {
            if (t == 0 || c >= 8) return;
            const unsigned* p = &g_rdy[((t << 2) + m_grp) * 8 + c];
            while (ld_acq(p) < 4u) __nanosleep(40);
        };
        // chunk c: c<8 -> A-hi 128-col block c (vs Whi AND Wlo); c>=8 -> A-lo (vs Whi)
        auto issue = [&](int c) {
            const int buf = c & 3;
            const __nv_bfloat16* Ab = A + (size_t)m0 * 2048
                                        + ((c >= 8) ? 1024 : 0) + ((c & 7) << 7);
            const uint32_t base = sbase + (uint32_t)(ABUF_OFF + buf * ABUF_SZ) * 4;
#pragma unroll
            for (int j = 0; j < 4; ++j) {
                int idx = tid + (j << 8);
                int row = idx >> 4, seg = idx & 15;
                CP_ASYNC16(base + (uint32_t)(row * A_STRIDE + seg * 4) * 4,
                           (const void*)(Ab + (size_t)row * 2048 + seg * 8));
            }
            CP_COMMIT();
        };

        wait_c(0); issue(0);
        wait_c(1); issue(1);
        wait_c(2); issue(2);

        for (int i = 0; i < NCHUNK; ++i) {
            if (i < NCHUNK - 2)      { CP_WAIT(2); }
            else if (i == NCHUNK - 2){ CP_WAIT(1); }
            else                     { CP_WAIT(0); }
            __syncthreads();

            const int abuf_w = ABUF_OFF + (i & 3) * ABUF_SZ;
            const int kw = (i & 7) << 6;           // chunk word offset in W rows
            const bool hi = (i < 8);

#pragma unroll
            for (int k16 = 0; k16 < 8; ++k16) {
                uint32_t af[4];
                ldsm4(af, sbase + (uint32_t)(abuf_w + a_lane_off + k16 * 8) * 4);
                const int kb = kw + k16 * 8;
                uint32_t bh_[4];
                ldsm4(bh_, sbase + (uint32_t)(b_lane_off + kb) * 4);
                mma16816(acc[0], af, bh_);
                mma16816(acc[1], af, bh_ + 2);
                if (hi) {
                    uint32_t bl_[4];
                    ldsm4(bl_, sbase + (uint32_t)(WLO_OFF + b_lane_off + kb) * 4);
                    mma16816(acc[0], af, bl_);
                    mma16816(acc[1], af, bl_ + 2);
                }
            }
            if (i + 3 < NCHUNK) { wait_c(i + 3); issue(i + 3); }
        }

        // ---- epilogue: tanh + blend; publish Anext; release; then out STG ----
#pragma unroll
        for (int nt = 0; nt < 2; ++nt) {
            const int c = n0 + wn * 16 + nt * 8 + tig * 2;
#pragma unroll
            for (int half = 0; half < 2; ++half) {
                const int row = m0 + wm * 16 + gid + half * 8;
                float tt, h0, h1;
                tt = tanh_fast(pre_r[nt][half].x + acc[nt][half * 2]);
                h0 = tt + rv[nt].x * (hprev[nt][half * 2] - tt);
                tt = tanh_fast(pre_r[nt][half].y + acc[nt][half * 2 + 1]);
                h1 = tt + rv[nt].y * (hprev[nt][half * 2 + 1] - tt);
                hprev[nt][half * 2]     = h0;
                hprev[nt][half * 2 + 1] = h1;

                if (t < T_DIM - 1) {
                    __nv_bfloat16 a0 = __float2bfloat16(h0);
                    __nv_bfloat16 a1 = __float2bfloat16(h1);
                    __nv_bfloat16* hip = Anext + (size_t)row * 2048 + c;
                    *(__nv_bfloat162*)hip = __nv_bfloat162(a0, a1);
                    __nv_bfloat16 l0 = __float2bfloat16(h0 - __bfloat162float(a0));
                    __nv_bfloat16 l1 = __float2bfloat16(h1 - __bfloat162float(a1));
                    *(__nv_bfloat162*)(hip + 1024) = __nv_bfloat162(l0, l1);
                }
            }
        }

        if (t < T_DIM - 1) {
            __threadfence();
            __syncthreads();
            if (tid == 0) {
                asm volatile("red.release.gpu.global.add.u32 [%0], 1;"
                    :: "l"(&g_rdy[(((t + 1) << 2) + m_grp) * 8 + (n_grp >> 2)])
                    : "memory");
            }
        }

        // deferred fp32 out store (off the inter-CTA critical path)
#pragma unroll
        for (int nt = 0; nt < 2; ++nt) {
            const int c = n0 + wn * 16 + nt * 8 + tig * 2;
#pragma unroll
            for (int half = 0; half < 2; ++half) {
                const int row = m0 + wm * 16 + gid + half * 8;
                *(float2*)(outt + (size_t)row * H_DIM + c) =
                    make_float2(hprev[nt][half * 2], hprev[nt][half * 2 + 1]);
            }
        }
    }
}

// ---------------------------------------------------------------------------
// Launch
// ---------------------------------------------------------------------------
extern "C" void kernel_launch(void* const* d_in, const int* in_sizes, int n_in,
                              void* d_out, int out_size) {
    const float* inputs  = (const float*)d_in[0];
    const float* hidden0 = (const float*)d_in[1];
    const float* actions = (const float*)d_in[2];
    const float* reward  = (const float*)d_in[3];
    const float* i2h     = (const float*)d_in[4];
    const float* h2h     = (const float*)d_in[5];
    const float* a2h     = (const float*)d_in[6];
    const float* r2h     = (const float*)d_in[7];
    const float* bh      = (const float*)d_in[8];
    const float* r       = (const float*)d_in[9];
    const void*  kact    = d_in[10];
    float* out = (float*)d_out;

    static int attr_done = 0;
    if (!attr_done) {
        cudaFuncSetAttribute(rnn_persistent,
                             cudaFuncAttributeMaxDynamicSharedMemorySize, SMEM_P_BYTES);
        attr_done = 1;
    }

    rbias_kernel<<<(B_DIM * H_DIM) / 256, 256>>>(reward, r2h, bh);
    wprep_kernel<<<dim3(32, 32), 256>>>(h2h);
    conv_h0_kernel<<<(B_DIM * H_DIM) / 256, 256>>>(hidden0);
    zero_rdy_kernel<<<8, 1024>>>();

    pre_kernel<<<T_DIM * B_DIM, 256>>>(inputs, actions, i2h, a2h, kact, out);

    rnn_persistent<<<GRID_P, 256, SMEM_P_BYTES>>>(hidden0, r, out);
}